// round 8
// baseline (speedup 1.0000x reference)
#include <cuda_runtime.h>
#include <cuda_bf16.h>
#include <cstddef>

constexpr int N_   = 50000;
constexpr int E_   = 800000;
constexpr int INC  = 128;
constexpr int HID  = 32;
constexpr int HEADS = 8;
constexpr int F1   = HEADS * HID;   // 256
constexpr int OUTC = 64;
constexpr float NEG_SLOPE = 0.2f;
constexpr int NB_SCAN = (N_ + 255) / 256;   // 196 scan blocks

// ---------------- scratch ----------------
__device__ float g_h1[(size_t)N_ * F1];     // layer1 GEMM out
__device__ float g_as1[N_ * HEADS];
__device__ float g_ad1[N_ * HEADS];
__device__ float g_hact[(size_t)N_ * F1];   // elu(layer1) -> GEMM2 input
__device__ float g_h2[(size_t)N_ * OUTC];
__device__ float g_as2[N_];
__device__ float g_ad2[N_];
__device__ int   g_deg[N_];
__device__ int   g_roff[N_ + 1];
__device__ int   g_cursor[N_];
__device__ int   g_csr_src[E_];
__device__ int   g_bsum[NB_SCAN];
__device__ int   g_boff[NB_SCAN];
__device__ int   g_is64;

// ---------------- init + dtype probe ----------------
__global__ void zero_deg_probe(const int* __restrict__ ei32) {
    int i = blockIdx.x * blockDim.x + threadIdx.x;
    if (i < N_) g_deg[i] = 0;
    if (i == 0) {
        int all_hi_zero = 1;
        #pragma unroll
        for (int k = 0; k < 16; k++)
            if (ei32[2 * k + 1] != 0) all_hi_zero = 0;
        g_is64 = all_hi_zero;   // int64 little-endian values < 2^31
    }
}

__device__ __forceinline__ int edge_src(const int* __restrict__ ei32, int i) {
    return g_is64 ? ei32[2 * (size_t)i] : ei32[i];
}
__device__ __forceinline__ int edge_dst(const int* __restrict__ ei32, int i) {
    return g_is64 ? ei32[2 * ((size_t)E_ + i)] : ei32[(size_t)E_ + i];
}

__global__ void count_deg(const int* __restrict__ ei32) {
    int i = blockIdx.x * blockDim.x + threadIdx.x;
    if (i >= E_) return;
    atomicAdd(&g_deg[edge_dst(ei32, i)], 1);
}

// ---------------- 3-phase grid scan of degrees ----------------
__global__ void scan_p1() {
    __shared__ int sh[256];
    int i = blockIdx.x * 256 + threadIdx.x;
    int v = (i < N_) ? g_deg[i] : 0;
    sh[threadIdx.x] = v;
    __syncthreads();
    #pragma unroll
    for (int off = 1; off < 256; off <<= 1) {
        int t = (threadIdx.x >= off) ? sh[threadIdx.x - off] : 0;
        __syncthreads();
        sh[threadIdx.x] += t;
        __syncthreads();
    }
    if (i < N_) g_roff[i] = sh[threadIdx.x] - v;
    if (threadIdx.x == 255) g_bsum[blockIdx.x] = sh[255];
}

__global__ void scan_p2() {
    __shared__ int sh[256];
    int v = (threadIdx.x < NB_SCAN) ? g_bsum[threadIdx.x] : 0;
    sh[threadIdx.x] = v;
    __syncthreads();
    #pragma unroll
    for (int off = 1; off < 256; off <<= 1) {
        int t = (threadIdx.x >= off) ? sh[threadIdx.x - off] : 0;
        __syncthreads();
        sh[threadIdx.x] += t;
        __syncthreads();
    }
    if (threadIdx.x < NB_SCAN) g_boff[threadIdx.x] = sh[threadIdx.x] - v;
    if (threadIdx.x == 255) g_roff[N_] = sh[255];
}

__global__ void scan_p3() {
    int i = blockIdx.x * 256 + threadIdx.x;
    if (i >= N_) return;
    int r = g_roff[i] + g_boff[blockIdx.x];
    g_roff[i] = r;
    g_cursor[i] = r;
}

__global__ void build_csr(const int* __restrict__ ei32) {
    int e = blockIdx.x * blockDim.x + threadIdx.x;
    if (e >= E_) return;
    int s = edge_src(ei32, e);
    int d = edge_dst(ei32, e);
    int pos = atomicAdd(&g_cursor[d], 1);
    g_csr_src[pos] = s;
}

// ---------------- SGEMM 128x128 tiles, 8x8 per thread (layer 1) -----------
__global__ void sgemm128x128(const float* __restrict__ A, const float* __restrict__ B,
                             float* __restrict__ C, int M, int K, int Ncol) {
    __shared__ float As[16][132];
    __shared__ float Bs[16][132];
    int tid  = threadIdx.x;
    int row0 = blockIdx.y * 128, col0 = blockIdx.x * 128;
    int tm = (tid >> 4) << 3;
    int tn = (tid & 15) << 3;
    float acc[8][8] = {};

    for (int k0 = 0; k0 < K; k0 += 16) {
        // A tile: 128x16 (8 floats per thread along k, transposed store)
        {
            int base = tid * 8;
            int mm = base >> 4, kk = base & 15;   // kk in {0,8}
            int r = row0 + mm;
            float4 a0 = make_float4(0.f, 0.f, 0.f, 0.f), a1 = a0;
            if (r < M) {
                a0 = *(const float4*)(A + (size_t)r * K + k0 + kk);
                a1 = *(const float4*)(A + (size_t)r * K + k0 + kk + 4);
            }
            As[kk + 0][mm] = a0.x; As[kk + 1][mm] = a0.y;
            As[kk + 2][mm] = a0.z; As[kk + 3][mm] = a0.w;
            As[kk + 4][mm] = a1.x; As[kk + 5][mm] = a1.y;
            As[kk + 6][mm] = a1.z; As[kk + 7][mm] = a1.w;
        }
        // B tile: 16x128 (8 floats per thread = 2 float4)
        {
            int base = tid * 8;
            int kk = base >> 7, nn = base & 127;
            const float* bp = B + (size_t)(k0 + kk) * Ncol + col0 + nn;
            float4 b0 = *(const float4*)bp;
            float4 b1 = *(const float4*)(bp + 4);
            Bs[kk][nn + 0] = b0.x; Bs[kk][nn + 1] = b0.y;
            Bs[kk][nn + 2] = b0.z; Bs[kk][nn + 3] = b0.w;
            Bs[kk][nn + 4] = b1.x; Bs[kk][nn + 5] = b1.y;
            Bs[kk][nn + 6] = b1.z; Bs[kk][nn + 7] = b1.w;
        }
        __syncthreads();
        #pragma unroll
        for (int kk = 0; kk < 16; kk++) {
            float4 a0 = *(const float4*)&As[kk][tm];
            float4 a1 = *(const float4*)&As[kk][tm + 4];
            float4 b0 = *(const float4*)&Bs[kk][tn];
            float4 b1 = *(const float4*)&Bs[kk][tn + 4];
            float a[8] = {a0.x, a0.y, a0.z, a0.w, a1.x, a1.y, a1.z, a1.w};
            float b[8] = {b0.x, b0.y, b0.z, b0.w, b1.x, b1.y, b1.z, b1.w};
            #pragma unroll
            for (int i = 0; i < 8; i++)
                #pragma unroll
                for (int j = 0; j < 8; j++)
                    acc[i][j] += a[i] * b[j];
        }
        __syncthreads();
    }
    #pragma unroll
    for (int i = 0; i < 8; i++) {
        int r = row0 + tm + i;
        if (r < M) {
            float* cp = C + (size_t)r * Ncol + col0 + tn;
            *(float4*)cp       = make_float4(acc[i][0], acc[i][1], acc[i][2], acc[i][3]);
            *(float4*)(cp + 4) = make_float4(acc[i][4], acc[i][5], acc[i][6], acc[i][7]);
        }
    }
}

// ---------------- SGEMM 128x64 tiles, 8x4 per thread (layer 2) ------------
__global__ void sgemm128x64(const float* __restrict__ A, const float* __restrict__ B,
                            float* __restrict__ C, int M, int K, int Ncol) {
    __shared__ float As[16][132];
    __shared__ float Bs[16][68];
    int tid  = threadIdx.x;
    int row0 = blockIdx.y * 128, col0 = blockIdx.x * 64;
    int tm = (tid >> 4) << 3;
    int tn = (tid & 15) << 2;
    float acc[8][4] = {};

    for (int k0 = 0; k0 < K; k0 += 16) {
        {
            int base = tid * 8;
            int mm = base >> 4, kk = base & 15;
            int r = row0 + mm;
            float4 a0 = make_float4(0.f, 0.f, 0.f, 0.f), a1 = a0;
            if (r < M) {
                a0 = *(const float4*)(A + (size_t)r * K + k0 + kk);
                a1 = *(const float4*)(A + (size_t)r * K + k0 + kk + 4);
            }
            As[kk + 0][mm] = a0.x; As[kk + 1][mm] = a0.y;
            As[kk + 2][mm] = a0.z; As[kk + 3][mm] = a0.w;
            As[kk + 4][mm] = a1.x; As[kk + 5][mm] = a1.y;
            As[kk + 6][mm] = a1.z; As[kk + 7][mm] = a1.w;
        }
        {
            int base = tid * 4;
            int kk = base >> 6, nn = base & 63;
            float4 bv = *(const float4*)(B + (size_t)(k0 + kk) * Ncol + col0 + nn);
            Bs[kk][nn] = bv.x; Bs[kk][nn + 1] = bv.y;
            Bs[kk][nn + 2] = bv.z; Bs[kk][nn + 3] = bv.w;
        }
        __syncthreads();
        #pragma unroll
        for (int kk = 0; kk < 16; kk++) {
            float4 a0 = *(const float4*)&As[kk][tm];
            float4 a1 = *(const float4*)&As[kk][tm + 4];
            float4 bv = *(const float4*)&Bs[kk][tn];
            float a[8] = {a0.x, a0.y, a0.z, a0.w, a1.x, a1.y, a1.z, a1.w};
            float b[4] = {bv.x, bv.y, bv.z, bv.w};
            #pragma unroll
            for (int i = 0; i < 8; i++)
                #pragma unroll
                for (int j = 0; j < 4; j++)
                    acc[i][j] += a[i] * b[j];
        }
        __syncthreads();
    }
    #pragma unroll
    for (int i = 0; i < 8; i++) {
        int r = row0 + tm + i;
        if (r < M) {
            float4 v = make_float4(acc[i][0], acc[i][1], acc[i][2], acc[i][3]);
            *(float4*)(C + (size_t)r * Ncol + col0 + tn) = v;
        }
    }
}

// ---------------- per-node attention coefficients ----------------
__global__ void alpha1_kernel(const float* __restrict__ a_src,
                              const float* __restrict__ a_dst) {
    int i = blockIdx.x * blockDim.x + threadIdx.x;
    if (i >= N_ * HEADS) return;
    int n = i >> 3, h = i & 7;
    const float4* hp = (const float4*)(g_h1 + (size_t)n * F1 + h * HID);
    const float4* sp = (const float4*)(a_src + h * HID);
    const float4* dp = (const float4*)(a_dst + h * HID);
    float s = 0.f, d = 0.f;
    #pragma unroll
    for (int q = 0; q < HID / 4; q++) {
        float4 hv = hp[q], sv = sp[q], dv = dp[q];
        s += hv.x * sv.x + hv.y * sv.y + hv.z * sv.z + hv.w * sv.w;
        d += hv.x * dv.x + hv.y * dv.y + hv.z * dv.z + hv.w * dv.w;
    }
    g_as1[i] = s; g_ad1[i] = d;
}

__global__ void alpha2_kernel(const float* __restrict__ a_src,
                              const float* __restrict__ a_dst) {
    int n = blockIdx.x * blockDim.x + threadIdx.x;
    if (n >= N_) return;
    const float4* hp = (const float4*)(g_h2 + (size_t)n * OUTC);
    const float4* sp = (const float4*)a_src;
    const float4* dp = (const float4*)a_dst;
    float s = 0.f, d = 0.f;
    #pragma unroll
    for (int q = 0; q < OUTC / 4; q++) {
        float4 hv = hp[q], sv = sp[q], dv = dp[q];
        s += hv.x * sv.x + hv.y * sv.y + hv.z * sv.z + hv.w * sv.w;
        d += hv.x * dv.x + hv.y * dv.y + hv.z * dv.z + hv.w * dv.w;
    }
    g_as2[n] = s; g_ad2[n] = d;
}

// ---------------- CSR aggregation layer 1: one warp per dst node ----------
__global__ void aggregate1(const float* __restrict__ b1) {
    __shared__ int   ss[8][32];
    __shared__ float ws[8][32][8];
    int w = (blockIdx.x * blockDim.x + threadIdx.x) >> 5;
    if (w >= N_) return;
    int lane = threadIdx.x & 31;
    int wb   = (threadIdx.x >> 5) & 7;
    int beg = g_roff[w], end = g_roff[w + 1];

    float ad[8];
    {
        float4 d0 = *(const float4*)(g_ad1 + w * 8);
        float4 d1 = *(const float4*)(g_ad1 + w * 8 + 4);
        ad[0] = d0.x; ad[1] = d0.y; ad[2] = d0.z; ad[3] = d0.w;
        ad[4] = d1.x; ad[5] = d1.y; ad[6] = d1.z; ad[7] = d1.w;
    }

    float acc[8] = {};
    float zp[8]  = {};
    int hsel = lane >> 2;

    for (int base = beg; base < end; base += 32) {
        int cnt = min(32, end - base);
        __syncwarp();
        if (base + lane < end) {
            int s = g_csr_src[base + lane];
            ss[wb][lane] = s;
            float4 s0 = *(const float4*)(g_as1 + s * 8);
            float4 s1 = *(const float4*)(g_as1 + s * 8 + 4);
            float ev[8] = {s0.x + ad[0], s0.y + ad[1], s0.z + ad[2], s0.w + ad[3],
                           s1.x + ad[4], s1.y + ad[5], s1.z + ad[6], s1.w + ad[7]};
            #pragma unroll
            for (int h = 0; h < 8; h++) {
                float e = ev[h];
                e = (e >= 0.f) ? e : NEG_SLOPE * e;
                float wv = __expf(e);
                ws[wb][lane][h] = wv;
                zp[h] += wv;
            }
        }
        __syncwarp();
        // unrolled x4 for MLP: 8 independent LDG.128 in flight
        int j = 0;
        for (; j + 4 <= cnt; j += 4) {
            int   s0 = ss[wb][j],     s1 = ss[wb][j + 1];
            int   s2 = ss[wb][j + 2], s3 = ss[wb][j + 3];
            float w0 = ws[wb][j][hsel],     w1 = ws[wb][j + 1][hsel];
            float w2 = ws[wb][j + 2][hsel], w3 = ws[wb][j + 3][hsel];
            const float* h0 = g_h1 + (size_t)s0 * F1 + lane * 8;
            const float* h1 = g_h1 + (size_t)s1 * F1 + lane * 8;
            const float* h2 = g_h1 + (size_t)s2 * F1 + lane * 8;
            const float* h3 = g_h1 + (size_t)s3 * F1 + lane * 8;
            float4 p00 = *(const float4*)h0,       p01 = *(const float4*)(h0 + 4);
            float4 p10 = *(const float4*)h1,       p11 = *(const float4*)(h1 + 4);
            float4 p20 = *(const float4*)h2,       p21 = *(const float4*)(h2 + 4);
            float4 p30 = *(const float4*)h3,       p31 = *(const float4*)(h3 + 4);
            acc[0] += w0 * p00.x + w1 * p10.x + w2 * p20.x + w3 * p30.x;
            acc[1] += w0 * p00.y + w1 * p10.y + w2 * p20.y + w3 * p30.y;
            acc[2] += w0 * p00.z + w1 * p10.z + w2 * p20.z + w3 * p30.z;
            acc[3] += w0 * p00.w + w1 * p10.w + w2 * p20.w + w3 * p30.w;
            acc[4] += w0 * p01.x + w1 * p11.x + w2 * p21.x + w3 * p31.x;
            acc[5] += w0 * p01.y + w1 * p11.y + w2 * p21.y + w3 * p31.y;
            acc[6] += w0 * p01.z + w1 * p11.z + w2 * p21.z + w3 * p31.z;
            acc[7] += w0 * p01.w + w1 * p11.w + w2 * p21.w + w3 * p31.w;
        }
        for (; j < cnt; j++) {
            int s = ss[wb][j];
            float wj = ws[wb][j][hsel];
            const float* hs = g_h1 + (size_t)s * F1 + lane * 8;
            float4 p0 = *(const float4*)hs;
            float4 p1 = *(const float4*)(hs + 4);
            acc[0] += wj * p0.x; acc[1] += wj * p0.y;
            acc[2] += wj * p0.z; acc[3] += wj * p0.w;
            acc[4] += wj * p1.x; acc[5] += wj * p1.y;
            acc[6] += wj * p1.z; acc[7] += wj * p1.w;
        }
    }

    #pragma unroll
    for (int h = 0; h < 8; h++)
        #pragma unroll
        for (int off = 16; off > 0; off >>= 1)
            zp[h] += __shfl_xor_sync(0xffffffffu, zp[h], off);
    float zu = zp[0];
    #pragma unroll
    for (int h = 1; h < 8; h++)
        if (hsel == h) zu = zp[h];

    float inv = (zu > 0.f) ? (1.f / zu) : 0.f;
    const float* bp = b1 + lane * 8;
    float4 b0 = *(const float4*)bp;
    float4 b1v = *(const float4*)(bp + 4);
    float bb[8] = {b0.x, b0.y, b0.z, b0.w, b1v.x, b1v.y, b1v.z, b1v.w};
    float o[8];
    #pragma unroll
    for (int q = 0; q < 8; q++) {
        float v = acc[q] * inv + bb[q];
        o[q] = (v > 0.f) ? v : (__expf(v) - 1.f);   // ELU
    }
    float* op = g_hact + (size_t)w * F1 + lane * 8;
    *(float4*)op       = make_float4(o[0], o[1], o[2], o[3]);
    *(float4*)(op + 4) = make_float4(o[4], o[5], o[6], o[7]);
}

// ---------------- CSR aggregation layer 2: one warp per dst node ----------
__global__ void aggregate2(const float* __restrict__ b2, float* __restrict__ out) {
    __shared__ int   ss[8][32];
    __shared__ float ws[8][32];
    int w = (blockIdx.x * blockDim.x + threadIdx.x) >> 5;
    if (w >= N_) return;
    int lane = threadIdx.x & 31;
    int wb   = (threadIdx.x >> 5) & 7;
    int beg = g_roff[w], end = g_roff[w + 1];
    float adn = g_ad2[w];

    float acc0 = 0.f, acc1 = 0.f, zp = 0.f;

    for (int base = beg; base < end; base += 32) {
        int cnt = min(32, end - base);
        __syncwarp();
        if (base + lane < end) {
            int s = g_csr_src[base + lane];
            ss[wb][lane] = s;
            float e = g_as2[s] + adn;
            e = (e >= 0.f) ? e : NEG_SLOPE * e;
            float wv = __expf(e);
            ws[wb][lane] = wv;
            zp += wv;
        }
        __syncwarp();
        int j = 0;
        for (; j + 4 <= cnt; j += 4) {
            int   s0 = ss[wb][j],     s1 = ss[wb][j + 1];
            int   s2 = ss[wb][j + 2], s3 = ss[wb][j + 3];
            float w0 = ws[wb][j],     w1 = ws[wb][j + 1];
            float w2 = ws[wb][j + 2], w3 = ws[wb][j + 3];
            float2 v0 = *(const float2*)(g_h2 + (size_t)s0 * OUTC + lane * 2);
            float2 v1 = *(const float2*)(g_h2 + (size_t)s1 * OUTC + lane * 2);
            float2 v2 = *(const float2*)(g_h2 + (size_t)s2 * OUTC + lane * 2);
            float2 v3 = *(const float2*)(g_h2 + (size_t)s3 * OUTC + lane * 2);
            acc0 += w0 * v0.x + w1 * v1.x + w2 * v2.x + w3 * v3.x;
            acc1 += w0 * v0.y + w1 * v1.y + w2 * v2.y + w3 * v3.y;
        }
        for (; j < cnt; j++) {
            int s = ss[wb][j];
            float wj = ws[wb][j];
            float2 hv = *(const float2*)(g_h2 + (size_t)s * OUTC + lane * 2);
            acc0 += wj * hv.x;
            acc1 += wj * hv.y;
        }
    }
    #pragma unroll
    for (int off = 16; off > 0; off >>= 1)
        zp += __shfl_xor_sync(0xffffffffu, zp, off);
    float inv = (zp > 0.f) ? (1.f / zp) : 0.f;
    float2 bv = *(const float2*)(b2 + lane * 2);
    float2 ov = make_float2(acc0 * inv + bv.x, acc1 * inv + bv.y);
    *(float2*)(out + (size_t)w * OUTC + lane * 2) = ov;
}

// ---------------- launch ----------------
extern "C" void kernel_launch(void* const* d_in, const int* in_sizes, int n_in,
                              void* d_out, int out_size) {
    const float* x    = (const float*)d_in[0];
    const int*   ei32 = (const int*)d_in[1];
    const float* W1   = (const float*)d_in[2];
    const float* a1s  = (const float*)d_in[3];
    const float* a1d  = (const float*)d_in[4];
    const float* b1   = (const float*)d_in[5];
    const float* W2   = (const float*)d_in[6];
    const float* a2s  = (const float*)d_in[7];
    const float* a2d  = (const float*)d_in[8];
    const float* b2   = (const float*)d_in[9];
    float* out = (float*)d_out;

    void* p;
    cudaGetSymbolAddress(&p, g_h1);   float* h1   = (float*)p;
    cudaGetSymbolAddress(&p, g_hact); float* hact = (float*)p;
    cudaGetSymbolAddress(&p, g_h2);   float* h2   = (float*)p;

    // graph build (CSR)
    zero_deg_probe<<<(N_ + 255) / 256, 256>>>(ei32);
    count_deg<<<(E_ + 255) / 256, 256>>>(ei32);
    scan_p1<<<NB_SCAN, 256>>>();
    scan_p2<<<1, 256>>>();
    scan_p3<<<NB_SCAN, 256>>>();
    build_csr<<<(E_ + 255) / 256, 256>>>(ei32);

    // layer 1
    {
        dim3 grid(F1 / 128, (N_ + 127) / 128);
        sgemm128x128<<<grid, 256>>>(x, W1, h1, N_, INC, F1);
    }
    alpha1_kernel<<<(N_ * HEADS + 255) / 256, 256>>>(a1s, a1d);
    aggregate1<<<(N_ * 32 + 255) / 256, 256>>>(b1);

    // layer 2
    {
        dim3 grid(OUTC / 64, (N_ + 127) / 128);
        sgemm128x64<<<grid, 256>>>(hact, W2, h2, N_, F1, OUTC);
    }
    alpha2_kernel<<<(N_ + 255) / 256, 256>>>(a2s, a2d);
    aggregate2<<<(N_ * 32 + 255) / 256, 256>>>(b2, out);
}

// round 9
// speedup vs baseline: 1.2277x; 1.2277x over previous
#include <cuda_runtime.h>
#include <cuda_bf16.h>
#include <cstddef>

constexpr int N_   = 50000;
constexpr int E_   = 800000;
constexpr int INC  = 128;
constexpr int HID  = 32;
constexpr int HEADS = 8;
constexpr int F1   = HEADS * HID;   // 256
constexpr int OUTC = 64;
constexpr float NEG_SLOPE = 0.2f;
constexpr int NB_SCAN = (N_ + 255) / 256;   // 196 scan blocks

// ---------------- scratch ----------------
__device__ float g_h1[(size_t)N_ * F1];     // layer1 GEMM out
__device__ float g_as1[N_ * HEADS];
__device__ float g_ad1[N_ * HEADS];
__device__ float g_hact[(size_t)N_ * F1];   // elu(layer1) -> GEMM2 input
__device__ float g_h2[(size_t)N_ * OUTC];
__device__ float g_as2[N_];
__device__ float g_ad2[N_];
__device__ int   g_deg[N_];
__device__ int   g_roff[N_ + 1];
__device__ int   g_cursor[N_];
__device__ int   g_csr_src[E_];
__device__ int   g_bsum[NB_SCAN];
__device__ int   g_boff[NB_SCAN];
__device__ int   g_is64;

// ---------------- init + dtype probe ----------------
__global__ void zero_deg_probe(const int* __restrict__ ei32) {
    int i = blockIdx.x * blockDim.x + threadIdx.x;
    if (i < N_) g_deg[i] = 0;
    if (i == 0) {
        int all_hi_zero = 1;
        #pragma unroll
        for (int k = 0; k < 16; k++)
            if (ei32[2 * k + 1] != 0) all_hi_zero = 0;
        g_is64 = all_hi_zero;   // int64 little-endian values < 2^31
    }
}

__device__ __forceinline__ int edge_src(const int* __restrict__ ei32, int i) {
    return g_is64 ? ei32[2 * (size_t)i] : ei32[i];
}
__device__ __forceinline__ int edge_dst(const int* __restrict__ ei32, int i) {
    return g_is64 ? ei32[2 * ((size_t)E_ + i)] : ei32[(size_t)E_ + i];
}

__global__ void count_deg(const int* __restrict__ ei32) {
    int i = blockIdx.x * blockDim.x + threadIdx.x;
    if (i >= E_) return;
    atomicAdd(&g_deg[edge_dst(ei32, i)], 1);
}

// ---------------- 3-phase grid scan of degrees ----------------
__global__ void scan_p1() {
    __shared__ int sh[256];
    int i = blockIdx.x * 256 + threadIdx.x;
    int v = (i < N_) ? g_deg[i] : 0;
    sh[threadIdx.x] = v;
    __syncthreads();
    #pragma unroll
    for (int off = 1; off < 256; off <<= 1) {
        int t = (threadIdx.x >= off) ? sh[threadIdx.x - off] : 0;
        __syncthreads();
        sh[threadIdx.x] += t;
        __syncthreads();
    }
    if (i < N_) g_roff[i] = sh[threadIdx.x] - v;
    if (threadIdx.x == 255) g_bsum[blockIdx.x] = sh[255];
}

__global__ void scan_p2() {
    __shared__ int sh[256];
    int v = (threadIdx.x < NB_SCAN) ? g_bsum[threadIdx.x] : 0;
    sh[threadIdx.x] = v;
    __syncthreads();
    #pragma unroll
    for (int off = 1; off < 256; off <<= 1) {
        int t = (threadIdx.x >= off) ? sh[threadIdx.x - off] : 0;
        __syncthreads();
        sh[threadIdx.x] += t;
        __syncthreads();
    }
    if (threadIdx.x < NB_SCAN) g_boff[threadIdx.x] = sh[threadIdx.x] - v;
    if (threadIdx.x == 255) g_roff[N_] = sh[255];
}

__global__ void scan_p3() {
    int i = blockIdx.x * 256 + threadIdx.x;
    if (i >= N_) return;
    int r = g_roff[i] + g_boff[blockIdx.x];
    g_roff[i] = r;
    g_cursor[i] = r;
}

__global__ void build_csr(const int* __restrict__ ei32) {
    int e = blockIdx.x * blockDim.x + threadIdx.x;
    if (e >= E_) return;
    int s = edge_src(ei32, e);
    int d = edge_dst(ei32, e);
    int pos = atomicAdd(&g_cursor[d], 1);
    g_csr_src[pos] = s;
}

// ---------------- SGEMM 128x64 tiles, 8x4/thread, fused alpha epilogue ----
// mode 1 (layer1): block cols = 2 heads of 32; per row, dot acc with
//   a_src/a_dst slices, width-8 shuffle reduce, leader lane stores as1/ad1.
// mode 2 (layer2): block cols = whole 64-wide a2; width-16 reduce -> as2/ad2.
// Tile ownership is exclusive per block => plain stores, no atomics.
__global__ void sgemm128x64(const float* __restrict__ A, const float* __restrict__ B,
                            float* __restrict__ C, int M, int K, int Ncol,
                            int mode, const float* __restrict__ a_src,
                            const float* __restrict__ a_dst) {
    __shared__ float As[16][132];
    __shared__ float Bs[16][68];
    int tid  = threadIdx.x;
    int row0 = blockIdx.y * 128, col0 = blockIdx.x * 64;
    int tm = (tid >> 4) << 3;
    int tn = (tid & 15) << 2;
    float acc[8][4] = {};

    for (int k0 = 0; k0 < K; k0 += 16) {
        {
            int base = tid * 8;
            int mm = base >> 4, kk = base & 15;
            int r = row0 + mm;
            float4 a0 = make_float4(0.f, 0.f, 0.f, 0.f), a1 = a0;
            if (r < M) {
                a0 = *(const float4*)(A + (size_t)r * K + k0 + kk);
                a1 = *(const float4*)(A + (size_t)r * K + k0 + kk + 4);
            }
            As[kk + 0][mm] = a0.x; As[kk + 1][mm] = a0.y;
            As[kk + 2][mm] = a0.z; As[kk + 3][mm] = a0.w;
            As[kk + 4][mm] = a1.x; As[kk + 5][mm] = a1.y;
            As[kk + 6][mm] = a1.z; As[kk + 7][mm] = a1.w;
        }
        {
            int base = tid * 4;
            int kk = base >> 6, nn = base & 63;
            float4 bv = *(const float4*)(B + (size_t)(k0 + kk) * Ncol + col0 + nn);
            Bs[kk][nn] = bv.x; Bs[kk][nn + 1] = bv.y;
            Bs[kk][nn + 2] = bv.z; Bs[kk][nn + 3] = bv.w;
        }
        __syncthreads();
        #pragma unroll
        for (int kk = 0; kk < 16; kk++) {
            float4 a0 = *(const float4*)&As[kk][tm];
            float4 a1 = *(const float4*)&As[kk][tm + 4];
            float4 bv = *(const float4*)&Bs[kk][tn];
            float a[8] = {a0.x, a0.y, a0.z, a0.w, a1.x, a1.y, a1.z, a1.w};
            float b[4] = {bv.x, bv.y, bv.z, bv.w};
            #pragma unroll
            for (int i = 0; i < 8; i++)
                #pragma unroll
                for (int j = 0; j < 4; j++)
                    acc[i][j] += a[i] * b[j];
        }
        __syncthreads();
    }
    #pragma unroll
    for (int i = 0; i < 8; i++) {
        int r = row0 + tm + i;
        if (r < M) {
            float4 v = make_float4(acc[i][0], acc[i][1], acc[i][2], acc[i][3]);
            *(float4*)(C + (size_t)r * Ncol + col0 + tn) = v;
        }
    }

    // ---- fused attention-coefficient epilogue ----
    if (mode == 1) {
        int gc = col0 + tn;            // global col
        int h  = gc >> 5;              // head index (constant per thread)
        int cc = gc & 31;              // col within head
        float4 asv = *(const float4*)(a_src + h * HID + cc);
        float4 adv = *(const float4*)(a_dst + h * HID + cc);
        #pragma unroll
        for (int i = 0; i < 8; i++) {
            float s = acc[i][0] * asv.x + acc[i][1] * asv.y
                    + acc[i][2] * asv.z + acc[i][3] * asv.w;
            float d = acc[i][0] * adv.x + acc[i][1] * adv.y
                    + acc[i][2] * adv.z + acc[i][3] * adv.w;
            #pragma unroll
            for (int off = 4; off > 0; off >>= 1) {
                s += __shfl_down_sync(0xffffffffu, s, off, 8);
                d += __shfl_down_sync(0xffffffffu, d, off, 8);
            }
            int r = row0 + tm + i;
            if ((tid & 7) == 0 && r < M) {
                g_as1[r * 8 + h] = s;
                g_ad1[r * 8 + h] = d;
            }
        }
    } else if (mode == 2) {
        int gc = col0 + tn;            // 0..60 (single 64-wide "head")
        float4 asv = *(const float4*)(a_src + gc);
        float4 adv = *(const float4*)(a_dst + gc);
        #pragma unroll
        for (int i = 0; i < 8; i++) {
            float s = acc[i][0] * asv.x + acc[i][1] * asv.y
                    + acc[i][2] * asv.z + acc[i][3] * asv.w;
            float d = acc[i][0] * adv.x + acc[i][1] * adv.y
                    + acc[i][2] * adv.z + acc[i][3] * adv.w;
            #pragma unroll
            for (int off = 8; off > 0; off >>= 1) {
                s += __shfl_down_sync(0xffffffffu, s, off, 16);
                d += __shfl_down_sync(0xffffffffu, d, off, 16);
            }
            int r = row0 + tm + i;
            if ((tid & 15) == 0 && r < M) {
                g_as2[r] = s;
                g_ad2[r] = d;
            }
        }
    }
}

// ---------------- CSR aggregation layer 1: one warp per dst node ----------
// lane owns channels c = lane*8 + q; head of lane = lane>>2.
// softmax without max-shift: shift-invariant; logits are O(1) (no overflow)
__global__ void aggregate1(const float* __restrict__ b1) {
    __shared__ int   ss[8][32];
    __shared__ float ws[8][32][8];
    int w = (blockIdx.x * blockDim.x + threadIdx.x) >> 5;
    if (w >= N_) return;
    int lane = threadIdx.x & 31;
    int wb   = (threadIdx.x >> 5) & 7;
    int beg = g_roff[w], end = g_roff[w + 1];

    float ad[8];
    {
        float4 d0 = *(const float4*)(g_ad1 + w * 8);
        float4 d1 = *(const float4*)(g_ad1 + w * 8 + 4);
        ad[0] = d0.x; ad[1] = d0.y; ad[2] = d0.z; ad[3] = d0.w;
        ad[4] = d1.x; ad[5] = d1.y; ad[6] = d1.z; ad[7] = d1.w;
    }

    float acc[8] = {};
    float zp[8]  = {};
    int hsel = lane >> 2;

    for (int base = beg; base < end; base += 32) {
        int cnt = min(32, end - base);
        __syncwarp();   // WAR vs previous chunk's reads
        if (base + lane < end) {
            int s = g_csr_src[base + lane];
            ss[wb][lane] = s;
            float4 s0 = *(const float4*)(g_as1 + s * 8);
            float4 s1 = *(const float4*)(g_as1 + s * 8 + 4);
            float ev[8] = {s0.x + ad[0], s0.y + ad[1], s0.z + ad[2], s0.w + ad[3],
                           s1.x + ad[4], s1.y + ad[5], s1.z + ad[6], s1.w + ad[7]};
            #pragma unroll
            for (int h = 0; h < 8; h++) {
                float e = ev[h];
                e = (e >= 0.f) ? e : NEG_SLOPE * e;
                float wv = __expf(e);
                ws[wb][lane][h] = wv;
                zp[h] += wv;
            }
        }
        __syncwarp();
        for (int j = 0; j < cnt; j++) {
            int s = ss[wb][j];
            float wj = ws[wb][j][hsel];
            const float* hs = g_h1 + (size_t)s * F1 + lane * 8;
            float4 p0 = *(const float4*)hs;
            float4 p1 = *(const float4*)(hs + 4);
            acc[0] += wj * p0.x; acc[1] += wj * p0.y;
            acc[2] += wj * p0.z; acc[3] += wj * p0.w;
            acc[4] += wj * p1.x; acc[5] += wj * p1.y;
            acc[6] += wj * p1.z; acc[7] += wj * p1.w;
        }
    }

    #pragma unroll
    for (int h = 0; h < 8; h++)
        #pragma unroll
        for (int off = 16; off > 0; off >>= 1)
            zp[h] += __shfl_xor_sync(0xffffffffu, zp[h], off);
    float zu = zp[0];
    #pragma unroll
    for (int h = 1; h < 8; h++)
        if (hsel == h) zu = zp[h];

    float inv = (zu > 0.f) ? (1.f / zu) : 0.f;
    const float* bp = b1 + lane * 8;
    float4 b0 = *(const float4*)bp;
    float4 b1v = *(const float4*)(bp + 4);
    float bb[8] = {b0.x, b0.y, b0.z, b0.w, b1v.x, b1v.y, b1v.z, b1v.w};
    float o[8];
    #pragma unroll
    for (int q = 0; q < 8; q++) {
        float v = acc[q] * inv + bb[q];
        o[q] = (v > 0.f) ? v : (__expf(v) - 1.f);   // ELU
    }
    float* op = g_hact + (size_t)w * F1 + lane * 8;
    *(float4*)op       = make_float4(o[0], o[1], o[2], o[3]);
    *(float4*)(op + 4) = make_float4(o[4], o[5], o[6], o[7]);
}

// ---------------- CSR aggregation layer 2: one warp per dst node ----------
__global__ void aggregate2(const float* __restrict__ b2, float* __restrict__ out) {
    __shared__ int   ss[8][32];
    __shared__ float ws[8][32];
    int w = (blockIdx.x * blockDim.x + threadIdx.x) >> 5;
    if (w >= N_) return;
    int lane = threadIdx.x & 31;
    int wb   = (threadIdx.x >> 5) & 7;
    int beg = g_roff[w], end = g_roff[w + 1];
    float adn = g_ad2[w];

    float acc0 = 0.f, acc1 = 0.f, zp = 0.f;

    for (int base = beg; base < end; base += 32) {
        int cnt = min(32, end - base);
        __syncwarp();
        if (base + lane < end) {
            int s = g_csr_src[base + lane];
            ss[wb][lane] = s;
            float e = g_as2[s] + adn;
            e = (e >= 0.f) ? e : NEG_SLOPE * e;
            float wv = __expf(e);
            ws[wb][lane] = wv;
            zp += wv;
        }
        __syncwarp();
        for (int j = 0; j < cnt; j++) {
            int s = ss[wb][j];
            float wj = ws[wb][j];
            float2 hv = *(const float2*)(g_h2 + (size_t)s * OUTC + lane * 2);
            acc0 += wj * hv.x;
            acc1 += wj * hv.y;
        }
    }
    #pragma unroll
    for (int off = 16; off > 0; off >>= 1)
        zp += __shfl_xor_sync(0xffffffffu, zp, off);
    float inv = (zp > 0.f) ? (1.f / zp) : 0.f;
    float2 bv = *(const float2*)(b2 + lane * 2);
    float2 ov = make_float2(acc0 * inv + bv.x, acc1 * inv + bv.y);
    *(float2*)(out + (size_t)w * OUTC + lane * 2) = ov;
}

// ---------------- launch ----------------
extern "C" void kernel_launch(void* const* d_in, const int* in_sizes, int n_in,
                              void* d_out, int out_size) {
    const float* x    = (const float*)d_in[0];
    const int*   ei32 = (const int*)d_in[1];
    const float* W1   = (const float*)d_in[2];
    const float* a1s  = (const float*)d_in[3];
    const float* a1d  = (const float*)d_in[4];
    const float* b1   = (const float*)d_in[5];
    const float* W2   = (const float*)d_in[6];
    const float* a2s  = (const float*)d_in[7];
    const float* a2d  = (const float*)d_in[8];
    const float* b2   = (const float*)d_in[9];
    float* out = (float*)d_out;

    void* p;
    cudaGetSymbolAddress(&p, g_h1);   float* h1   = (float*)p;
    cudaGetSymbolAddress(&p, g_hact); float* hact = (float*)p;
    cudaGetSymbolAddress(&p, g_h2);   float* h2   = (float*)p;

    // graph build (CSR)
    zero_deg_probe<<<(N_ + 255) / 256, 256>>>(ei32);
    count_deg<<<(E_ + 255) / 256, 256>>>(ei32);
    scan_p1<<<NB_SCAN, 256>>>();
    scan_p2<<<1, 256>>>();
    scan_p3<<<NB_SCAN, 256>>>();
    build_csr<<<(E_ + 255) / 256, 256>>>(ei32);

    // layer 1 (alpha fused into GEMM epilogue, mode 1)
    {
        dim3 grid(F1 / 64, (N_ + 127) / 128);
        sgemm128x64<<<grid, 256>>>(x, W1, h1, N_, INC, F1, 1, a1s, a1d);
    }
    aggregate1<<<(N_ * 32 + 255) / 256, 256>>>(b1);

    // layer 2 (alpha fused, mode 2)
    {
        dim3 grid(OUTC / 64, (N_ + 127) / 128);
        sgemm128x64<<<grid, 256>>>(hact, W2, h2, N_, F1, OUTC, 2, a2s, a2d);
    }
    aggregate2<<<(N_ * 32 + 255) / 256, 256>>>(b2, out);
}

// round 11
// speedup vs baseline: 1.2641x; 1.0296x over previous
#include <cuda_runtime.h>
#include <cuda_bf16.h>
#include <cstddef>

constexpr int N_   = 50000;
constexpr int E_   = 800000;
constexpr int INC  = 128;
constexpr int HID  = 32;
constexpr int HEADS = 8;
constexpr int F1   = HEADS * HID;   // 256
constexpr int OUTC = 64;
constexpr float NEG_SLOPE = 0.2f;
constexpr int NB_SCAN = (N_ + 255) / 256;   // 196 scan blocks

// ---------------- scratch ----------------
__device__ float g_h1[(size_t)N_ * F1];     // layer1 GEMM out
__device__ float g_as1[N_ * HEADS];
__device__ float g_ad1[N_ * HEADS];
__device__ float g_hact[(size_t)N_ * F1];   // elu(layer1) -> GEMM2 input
__device__ float g_h2[(size_t)N_ * OUTC];
__device__ float g_as2[N_];
__device__ float g_ad2[N_];
__device__ int   g_deg[N_];
__device__ int   g_roff[N_ + 1];
__device__ int   g_cursor[N_];
__device__ int   g_csr_src[E_];
__device__ int   g_bsum[NB_SCAN];
__device__ int   g_boff[NB_SCAN];
__device__ int   g_is64;

// ---------------- init + dtype probe ----------------
__global__ void zero_deg_probe(const int* __restrict__ ei32) {
    int i = blockIdx.x * blockDim.x + threadIdx.x;
    if (i < N_) g_deg[i] = 0;
    if (i == 0) {
        int all_hi_zero = 1;
        #pragma unroll
        for (int k = 0; k < 16; k++)
            if (ei32[2 * k + 1] != 0) all_hi_zero = 0;
        g_is64 = all_hi_zero;   // int64 little-endian values < 2^31
    }
}

__device__ __forceinline__ int edge_src(const int* __restrict__ ei32, int i) {
    return g_is64 ? ei32[2 * (size_t)i] : ei32[i];
}
__device__ __forceinline__ int edge_dst(const int* __restrict__ ei32, int i) {
    return g_is64 ? ei32[2 * ((size_t)E_ + i)] : ei32[(size_t)E_ + i];
}

__global__ void count_deg(const int* __restrict__ ei32) {
    int i = blockIdx.x * blockDim.x + threadIdx.x;
    if (i >= E_) return;
    atomicAdd(&g_deg[edge_dst(ei32, i)], 1);
}

// ---------------- 3-phase grid scan of degrees ----------------
__global__ void scan_p1() {
    __shared__ int sh[256];
    int i = blockIdx.x * 256 + threadIdx.x;
    int v = (i < N_) ? g_deg[i] : 0;
    sh[threadIdx.x] = v;
    __syncthreads();
    #pragma unroll
    for (int off = 1; off < 256; off <<= 1) {
        int t = (threadIdx.x >= off) ? sh[threadIdx.x - off] : 0;
        __syncthreads();
        sh[threadIdx.x] += t;
        __syncthreads();
    }
    if (i < N_) g_roff[i] = sh[threadIdx.x] - v;
    if (threadIdx.x == 255) g_bsum[blockIdx.x] = sh[255];
}

__global__ void scan_p2() {
    __shared__ int sh[256];
    int v = (threadIdx.x < NB_SCAN) ? g_bsum[threadIdx.x] : 0;
    sh[threadIdx.x] = v;
    __syncthreads();
    #pragma unroll
    for (int off = 1; off < 256; off <<= 1) {
        int t = (threadIdx.x >= off) ? sh[threadIdx.x - off] : 0;
        __syncthreads();
        sh[threadIdx.x] += t;
        __syncthreads();
    }
    if (threadIdx.x < NB_SCAN) g_boff[threadIdx.x] = sh[threadIdx.x] - v;
    if (threadIdx.x == 255) g_roff[N_] = sh[255];
}

__global__ void scan_p3() {
    int i = blockIdx.x * 256 + threadIdx.x;
    if (i >= N_) return;
    int r = g_roff[i] + g_boff[blockIdx.x];
    g_roff[i] = r;
    g_cursor[i] = r;
}

__global__ void build_csr(const int* __restrict__ ei32) {
    int e = blockIdx.x * blockDim.x + threadIdx.x;
    if (e >= E_) return;
    int s = edge_src(ei32, e);
    int d = edge_dst(ei32, e);
    int pos = atomicAdd(&g_cursor[d], 1);
    g_csr_src[pos] = s;
}

// ---------------- SGEMM 128x64, 8x4/thread, DOUBLE-BUFFERED smem ----------
// One __syncthreads per K-chunk; next chunk's global loads prefetched into
// registers before computing the current chunk. Fused alpha epilogue:
//   mode 1: width-8 shuffle reduce -> as1/ad1 (2 heads per block-col tile)
//   mode 2: width-16 shuffle reduce -> as2/ad2
__global__ void sgemm128x64(const float* __restrict__ A, const float* __restrict__ B,
                            float* __restrict__ C, int M, int K, int Ncol,
                            int mode, const float* __restrict__ a_src,
                            const float* __restrict__ a_dst) {
    __shared__ float As[2][16][132];
    __shared__ float Bs[2][16][68];
    int tid  = threadIdx.x;
    int row0 = blockIdx.y * 128, col0 = blockIdx.x * 64;
    int tm = (tid >> 4) << 3;
    int tn = (tid & 15) << 2;
    float acc[8][4] = {};

    // loader lane assignments (fixed per thread)
    int abase = tid * 8;
    int amm = abase >> 4, akk = abase & 15;     // akk in {0,8}
    int ar  = row0 + amm;
    int bbase = tid * 4;
    int bkk = bbase >> 6, bnn = bbase & 63;

    const int nsteps = K / 16;

    // prologue: load chunk 0 -> buffer 0
    {
        float4 a0 = make_float4(0.f, 0.f, 0.f, 0.f), a1 = a0;
        if (ar < M) {
            a0 = *(const float4*)(A + (size_t)ar * K + akk);
            a1 = *(const float4*)(A + (size_t)ar * K + akk + 4);
        }
        float4 bv = *(const float4*)(B + (size_t)bkk * Ncol + col0 + bnn);
        As[0][akk + 0][amm] = a0.x; As[0][akk + 1][amm] = a0.y;
        As[0][akk + 2][amm] = a0.z; As[0][akk + 3][amm] = a0.w;
        As[0][akk + 4][amm] = a1.x; As[0][akk + 5][amm] = a1.y;
        As[0][akk + 6][amm] = a1.z; As[0][akk + 7][amm] = a1.w;
        Bs[0][bkk][bnn]     = bv.x; Bs[0][bkk][bnn + 1] = bv.y;
        Bs[0][bkk][bnn + 2] = bv.z; Bs[0][bkk][bnn + 3] = bv.w;
    }
    __syncthreads();

    for (int s = 0; s < nsteps; s++) {
        int buf = s & 1;
        bool has_next = (s + 1 < nsteps);
        float4 na0, na1, nbv;
        if (has_next) {
            int k0 = (s + 1) * 16;
            na0 = make_float4(0.f, 0.f, 0.f, 0.f); na1 = na0;
            if (ar < M) {
                na0 = *(const float4*)(A + (size_t)ar * K + k0 + akk);
                na1 = *(const float4*)(A + (size_t)ar * K + k0 + akk + 4);
            }
            nbv = *(const float4*)(B + (size_t)(k0 + bkk) * Ncol + col0 + bnn);
        }
        #pragma unroll
        for (int kk = 0; kk < 16; kk++) {
            float4 a0 = *(const float4*)&As[buf][kk][tm];
            float4 a1 = *(const float4*)&As[buf][kk][tm + 4];
            float4 bv = *(const float4*)&Bs[buf][kk][tn];
            float a[8] = {a0.x, a0.y, a0.z, a0.w, a1.x, a1.y, a1.z, a1.w};
            float b[4] = {bv.x, bv.y, bv.z, bv.w};
            #pragma unroll
            for (int i = 0; i < 8; i++)
                #pragma unroll
                for (int j = 0; j < 4; j++)
                    acc[i][j] += a[i] * b[j];
        }
        if (has_next) {
            int nb = buf ^ 1;
            As[nb][akk + 0][amm] = na0.x; As[nb][akk + 1][amm] = na0.y;
            As[nb][akk + 2][amm] = na0.z; As[nb][akk + 3][amm] = na0.w;
            As[nb][akk + 4][amm] = na1.x; As[nb][akk + 5][amm] = na1.y;
            As[nb][akk + 6][amm] = na1.z; As[nb][akk + 7][amm] = na1.w;
            Bs[nb][bkk][bnn]     = nbv.x; Bs[nb][bkk][bnn + 1] = nbv.y;
            Bs[nb][bkk][bnn + 2] = nbv.z; Bs[nb][bkk][bnn + 3] = nbv.w;
            __syncthreads();
        }
    }

    #pragma unroll
    for (int i = 0; i < 8; i++) {
        int r = row0 + tm + i;
        if (r < M) {
            float4 v = make_float4(acc[i][0], acc[i][1], acc[i][2], acc[i][3]);
            *(float4*)(C + (size_t)r * Ncol + col0 + tn) = v;
        }
    }

    // ---- fused attention-coefficient epilogue ----
    if (mode == 1) {
        int gc = col0 + tn;
        int h  = gc >> 5;
        int cc = gc & 31;
        float4 asv = *(const float4*)(a_src + h * HID + cc);
        float4 adv = *(const float4*)(a_dst + h * HID + cc);
        #pragma unroll
        for (int i = 0; i < 8; i++) {
            float sv = acc[i][0] * asv.x + acc[i][1] * asv.y
                     + acc[i][2] * asv.z + acc[i][3] * asv.w;
            float dv = acc[i][0] * adv.x + acc[i][1] * adv.y
                     + acc[i][2] * adv.z + acc[i][3] * adv.w;
            #pragma unroll
            for (int off = 4; off > 0; off >>= 1) {
                sv += __shfl_down_sync(0xffffffffu, sv, off, 8);
                dv += __shfl_down_sync(0xffffffffu, dv, off, 8);
            }
            int r = row0 + tm + i;
            if ((tid & 7) == 0 && r < M) {
                g_as1[r * 8 + h] = sv;
                g_ad1[r * 8 + h] = dv;
            }
        }
    } else if (mode == 2) {
        int gc = col0 + tn;
        float4 asv = *(const float4*)(a_src + gc);
        float4 adv = *(const float4*)(a_dst + gc);
        #pragma unroll
        for (int i = 0; i < 8; i++) {
            float sv = acc[i][0] * asv.x + acc[i][1] * asv.y
                     + acc[i][2] * asv.z + acc[i][3] * asv.w;
            float dv = acc[i][0] * adv.x + acc[i][1] * adv.y
                     + acc[i][2] * adv.z + acc[i][3] * adv.w;
            #pragma unroll
            for (int off = 8; off > 0; off >>= 1) {
                sv += __shfl_down_sync(0xffffffffu, sv, off, 16);
                dv += __shfl_down_sync(0xffffffffu, dv, off, 16);
            }
            int r = row0 + tm + i;
            if ((tid & 15) == 0 && r < M) {
                g_as2[r] = sv;
                g_ad2[r] = dv;
            }
        }
    }
}

// ---------------- CSR aggregation layer 1: one warp per dst node ----------
// lane owns channels c = lane*8 + q; head of lane = lane>>2.
// softmax without max-shift: shift-invariant; logits are O(1) (no overflow)
__global__ void aggregate1(const float* __restrict__ b1) {
    __shared__ int   ss[8][32];
    __shared__ float ws[8][32][8];
    int w = (blockIdx.x * blockDim.x + threadIdx.x) >> 5;
    if (w >= N_) return;
    int lane = threadIdx.x & 31;
    int wb   = (threadIdx.x >> 5) & 7;
    int beg = g_roff[w], end = g_roff[w + 1];

    float ad[8];
    {
        float4 d0 = *(const float4*)(g_ad1 + w * 8);
        float4 d1 = *(const float4*)(g_ad1 + w * 8 + 4);
        ad[0] = d0.x; ad[1] = d0.y; ad[2] = d0.z; ad[3] = d0.w;
        ad[4] = d1.x; ad[5] = d1.y; ad[6] = d1.z; ad[7] = d1.w;
    }

    float acc[8] = {};
    float zp[8]  = {};
    int hsel = lane >> 2;

    for (int base = beg; base < end; base += 32) {
        int cnt = min(32, end - base);
        __syncwarp();   // WAR vs previous chunk's reads
        if (base + lane < end) {
            int s = g_csr_src[base + lane];
            ss[wb][lane] = s;
            float4 s0 = *(const float4*)(g_as1 + s * 8);
            float4 s1 = *(const float4*)(g_as1 + s * 8 + 4);
            float ev[8] = {s0.x + ad[0], s0.y + ad[1], s0.z + ad[2], s0.w + ad[3],
                           s1.x + ad[4], s1.y + ad[5], s1.z + ad[6], s1.w + ad[7]};
            #pragma unroll
            for (int h = 0; h < 8; h++) {
                float e = ev[h];
                e = (e >= 0.f) ? e : NEG_SLOPE * e;
                float wv = __expf(e);
                ws[wb][lane][h] = wv;
                zp[h] += wv;
            }
        }
        __syncwarp();
        for (int j = 0; j < cnt; j++) {
            int s = ss[wb][j];
            float wj = ws[wb][j][hsel];
            const float* hs = g_h1 + (size_t)s * F1 + lane * 8;
            float4 p0 = *(const float4*)hs;
            float4 p1 = *(const float4*)(hs + 4);
            acc[0] += wj * p0.x; acc[1] += wj * p0.y;
            acc[2] += wj * p0.z; acc[3] += wj * p0.w;
            acc[4] += wj * p1.x; acc[5] += wj * p1.y;
            acc[6] += wj * p1.z; acc[7] += wj * p1.w;
        }
    }

    #pragma unroll
    for (int h = 0; h < 8; h++)
        #pragma unroll
        for (int off = 16; off > 0; off >>= 1)
            zp[h] += __shfl_xor_sync(0xffffffffu, zp[h], off);
    float zu = zp[0];
    #pragma unroll
    for (int h = 1; h < 8; h++)
        if (hsel == h) zu = zp[h];

    float inv = (zu > 0.f) ? (1.f / zu) : 0.f;
    const float* bp = b1 + lane * 8;
    float4 b0 = *(const float4*)bp;
    float4 b1v = *(const float4*)(bp + 4);
    float bb[8] = {b0.x, b0.y, b0.z, b0.w, b1v.x, b1v.y, b1v.z, b1v.w};
    float o[8];
    #pragma unroll
    for (int q = 0; q < 8; q++) {
        float v = acc[q] * inv + bb[q];
        o[q] = (v > 0.f) ? v : (__expf(v) - 1.f);   // ELU
    }
    float* op = g_hact + (size_t)w * F1 + lane * 8;
    *(float4*)op       = make_float4(o[0], o[1], o[2], o[3]);
    *(float4*)(op + 4) = make_float4(o[4], o[5], o[6], o[7]);
}

// ---------------- CSR aggregation layer 2: one warp per dst node ----------
__global__ void aggregate2(const float* __restrict__ b2, float* __restrict__ out) {
    __shared__ int   ss[8][32];
    __shared__ float ws[8][32];
    int w = (blockIdx.x * blockDim.x + threadIdx.x) >> 5;
    if (w >= N_) return;
    int lane = threadIdx.x & 31;
    int wb   = (threadIdx.x >> 5) & 7;
    int beg = g_roff[w], end = g_roff[w + 1];
    float adn = g_ad2[w];

    float acc0 = 0.f, acc1 = 0.f, zp = 0.f;

    for (int base = beg; base < end; base += 32) {
        int cnt = min(32, end - base);
        __syncwarp();
        if (base + lane < end) {
            int s = g_csr_src[base + lane];
            ss[wb][lane] = s;
            float e = g_as2[s] + adn;
            e = (e >= 0.f) ? e : NEG_SLOPE * e;
            float wv = __expf(e);
            ws[wb][lane] = wv;
            zp += wv;
        }
        __syncwarp();
        for (int j = 0; j < cnt; j++) {
            int s = ss[wb][j];
            float wj = ws[wb][j];
            float2 hv = *(const float2*)(g_h2 + (size_t)s * OUTC + lane * 2);
            acc0 += wj * hv.x;
            acc1 += wj * hv.y;
        }
    }
    #pragma unroll
    for (int off = 16; off > 0; off >>= 1)
        zp += __shfl_xor_sync(0xffffffffu, zp, off);
    float inv = (zp > 0.f) ? (1.f / zp) : 0.f;
    float2 bv = *(const float2*)(b2 + lane * 2);
    float2 ov = make_float2(acc0 * inv + bv.x, acc1 * inv + bv.y);
    *(float2*)(out + (size_t)w * OUTC + lane * 2) = ov;
}

// ---------------- launch ----------------
extern "C" void kernel_launch(void* const* d_in, const int* in_sizes, int n_in,
                              void* d_out, int out_size) {
    const float* x    = (const float*)d_in[0];
    const int*   ei32 = (const int*)d_in[1];
    const float* W1   = (const float*)d_in[2];
    const float* a1s  = (const float*)d_in[3];
    const float* a1d  = (const float*)d_in[4];
    const float* b1   = (const float*)d_in[5];
    const float* W2   = (const float*)d_in[6];
    const float* a2s  = (const float*)d_in[7];
    const float* a2d  = (const float*)d_in[8];
    const float* b2   = (const float*)d_in[9];
    float* out = (float*)d_out;

    void* p;
    cudaGetSymbolAddress(&p, g_h1);   float* h1   = (float*)p;
    cudaGetSymbolAddress(&p, g_hact); float* hact = (float*)p;
    cudaGetSymbolAddress(&p, g_h2);   float* h2   = (float*)p;

    // graph build (CSR)
    zero_deg_probe<<<(N_ + 255) / 256, 256>>>(ei32);
    count_deg<<<(E_ + 255) / 256, 256>>>(ei32);
    scan_p1<<<NB_SCAN, 256>>>();
    scan_p2<<<1, 256>>>();
    scan_p3<<<NB_SCAN, 256>>>();
    build_csr<<<(E_ + 255) / 256, 256>>>(ei32);

    // layer 1 (alpha fused into GEMM epilogue, mode 1)
    {
        dim3 grid(F1 / 64, (N_ + 127) / 128);
        sgemm128x64<<<grid, 256>>>(x, W1, h1, N_, INC, F1, 1, a1s, a1d);
    }
    aggregate1<<<(N_ * 32 + 255) / 256, 256>>>(b1);

    // layer 2 (alpha fused, mode 2)
    {
        dim3 grid(OUTC / 64, (N_ + 127) / 128);
        sgemm128x64<<<grid, 256>>>(hact, W2, h2, N_, F1, OUTC, 2, a2s, a2d);
    }
    aggregate2<<<(N_ * 32 + 255) / 256, 256>>>(b2, out);
}

// round 17
// speedup vs baseline: 1.3278x; 1.0504x over previous
#include <cuda_runtime.h>
#include <cuda_bf16.h>
#include <cstddef>

constexpr int N_   = 50000;
constexpr int E_   = 800000;
constexpr int INC  = 128;
constexpr int HID  = 32;
constexpr int HEADS = 8;
constexpr int F1   = HEADS * HID;   // 256
constexpr int OUTC = 64;
constexpr float NEG_SLOPE = 0.2f;
constexpr int NB_SCAN = (N_ + 255) / 256;   // 196 scan blocks

// ---------------- scratch ----------------
__device__ float g_h1[(size_t)N_ * F1];     // layer1 GEMM out
__device__ float g_as1[N_ * HEADS];
__device__ float g_ad1[N_ * HEADS];
__device__ float g_hact[(size_t)N_ * F1];   // elu(layer1) -> GEMM2 input
__device__ float g_h2[(size_t)N_ * OUTC];
__device__ float g_as2[N_];
__device__ float g_ad2[N_];
__device__ int   g_deg[N_];
__device__ int   g_roff[N_ + 1];
__device__ int   g_cursor[N_];
__device__ int   g_csr_src[E_];
__device__ int   g_bsum[NB_SCAN];
__device__ int   g_boff[NB_SCAN];
__device__ int   g_is64;

// ---------------- side stream for graph-build overlap ----------------
// Created once at static-init time (stream/event creation only — no device
// memory allocation). kernel_launch performs the identical record/wait/launch
// sequence on every call (deterministic).
struct SideStream {
    cudaStream_t s2 = nullptr;
    cudaEvent_t  fork = nullptr, join = nullptr;
    SideStream() {
        if (cudaStreamCreateWithFlags(&s2, cudaStreamNonBlocking) != cudaSuccess)
            s2 = nullptr;
        cudaEventCreateWithFlags(&fork, cudaEventDisableTiming);
        cudaEventCreateWithFlags(&join, cudaEventDisableTiming);
    }
};
static SideStream g_ss;

// ---------------- init + dtype probe ----------------
__global__ void zero_deg_probe(const int* __restrict__ ei32) {
    int i = blockIdx.x * blockDim.x + threadIdx.x;
    if (i < N_) g_deg[i] = 0;
    if (i == 0) {
        int all_hi_zero = 1;
        #pragma unroll
        for (int k = 0; k < 16; k++)
            if (ei32[2 * k + 1] != 0) all_hi_zero = 0;
        g_is64 = all_hi_zero;   // int64 little-endian values < 2^31
    }
}

__device__ __forceinline__ int edge_src(const int* __restrict__ ei32, int i) {
    return g_is64 ? ei32[2 * (size_t)i] : ei32[i];
}
__device__ __forceinline__ int edge_dst(const int* __restrict__ ei32, int i) {
    return g_is64 ? ei32[2 * ((size_t)E_ + i)] : ei32[(size_t)E_ + i];
}

__global__ void count_deg(const int* __restrict__ ei32) {
    int i = blockIdx.x * blockDim.x + threadIdx.x;
    if (i >= E_) return;
    atomicAdd(&g_deg[edge_dst(ei32, i)], 1);
}

// ---------------- 3-phase grid scan of degrees ----------------
__global__ void scan_p1() {
    __shared__ int sh[256];
    int i = blockIdx.x * 256 + threadIdx.x;
    int v = (i < N_) ? g_deg[i] : 0;
    sh[threadIdx.x] = v;
    __syncthreads();
    #pragma unroll
    for (int off = 1; off < 256; off <<= 1) {
        int t = (threadIdx.x >= off) ? sh[threadIdx.x - off] : 0;
        __syncthreads();
        sh[threadIdx.x] += t;
        __syncthreads();
    }
    if (i < N_) g_roff[i] = sh[threadIdx.x] - v;
    if (threadIdx.x == 255) g_bsum[blockIdx.x] = sh[255];
}

__global__ void scan_p2() {
    __shared__ int sh[256];
    int v = (threadIdx.x < NB_SCAN) ? g_bsum[threadIdx.x] : 0;
    sh[threadIdx.x] = v;
    __syncthreads();
    #pragma unroll
    for (int off = 1; off < 256; off <<= 1) {
        int t = (threadIdx.x >= off) ? sh[threadIdx.x - off] : 0;
        __syncthreads();
        sh[threadIdx.x] += t;
        __syncthreads();
    }
    if (threadIdx.x < NB_SCAN) g_boff[threadIdx.x] = sh[threadIdx.x] - v;
    if (threadIdx.x == 255) g_roff[N_] = sh[255];
}

__global__ void scan_p3() {
    int i = blockIdx.x * 256 + threadIdx.x;
    if (i >= N_) return;
    int r = g_roff[i] + g_boff[blockIdx.x];
    g_roff[i] = r;
    g_cursor[i] = r;
}

__global__ void build_csr(const int* __restrict__ ei32) {
    int e = blockIdx.x * blockDim.x + threadIdx.x;
    if (e >= E_) return;
    int s = edge_src(ei32, e);
    int d = edge_dst(ei32, e);
    int pos = atomicAdd(&g_cursor[d], 1);
    g_csr_src[pos] = s;
}

// ---------------- SGEMM 128x64, 8x4/thread, DOUBLE-BUFFERED smem ----------
// Fused alpha epilogue:
//   mode 1: width-8 shuffle reduce -> as1/ad1 (2 heads per block-col tile)
//   mode 2: width-16 shuffle reduce -> as2/ad2
__global__ void sgemm128x64(const float* __restrict__ A, const float* __restrict__ B,
                            float* __restrict__ C, int M, int K, int Ncol,
                            int mode, const float* __restrict__ a_src,
                            const float* __restrict__ a_dst) {
    __shared__ float As[2][16][132];
    __shared__ float Bs[2][16][68];
    int tid  = threadIdx.x;
    int row0 = blockIdx.y * 128, col0 = blockIdx.x * 64;
    int tm = (tid >> 4) << 3;
    int tn = (tid & 15) << 2;
    float acc[8][4] = {};

    int abase = tid * 8;
    int amm = abase >> 4, akk = abase & 15;
    int ar  = row0 + amm;
    int bbase = tid * 4;
    int bkk = bbase >> 6, bnn = bbase & 63;

    const int nsteps = K / 16;

    {
        float4 a0 = make_float4(0.f, 0.f, 0.f, 0.f), a1 = a0;
        if (ar < M) {
            a0 = *(const float4*)(A + (size_t)ar * K + akk);
            a1 = *(const float4*)(A + (size_t)ar * K + akk + 4);
        }
        float4 bv = *(const float4*)(B + (size_t)bkk * Ncol + col0 + bnn);
        As[0][akk + 0][amm] = a0.x; As[0][akk + 1][amm] = a0.y;
        As[0][akk + 2][amm] = a0.z; As[0][akk + 3][amm] = a0.w;
        As[0][akk + 4][amm] = a1.x; As[0][akk + 5][amm] = a1.y;
        As[0][akk + 6][amm] = a1.z; As[0][akk + 7][amm] = a1.w;
        Bs[0][bkk][bnn]     = bv.x; Bs[0][bkk][bnn + 1] = bv.y;
        Bs[0][bkk][bnn + 2] = bv.z; Bs[0][bkk][bnn + 3] = bv.w;
    }
    __syncthreads();

    for (int s = 0; s < nsteps; s++) {
        int buf = s & 1;
        bool has_next = (s + 1 < nsteps);
        float4 na0, na1, nbv;
        if (has_next) {
            int k0 = (s + 1) * 16;
            na0 = make_float4(0.f, 0.f, 0.f, 0.f); na1 = na0;
            if (ar < M) {
                na0 = *(const float4*)(A + (size_t)ar * K + k0 + akk);
                na1 = *(const float4*)(A + (size_t)ar * K + k0 + akk + 4);
            }
            nbv = *(const float4*)(B + (size_t)(k0 + bkk) * Ncol + col0 + bnn);
        }
        #pragma unroll
        for (int kk = 0; kk < 16; kk++) {
            float4 a0 = *(const float4*)&As[buf][kk][tm];
            float4 a1 = *(const float4*)&As[buf][kk][tm + 4];
            float4 bv = *(const float4*)&Bs[buf][kk][tn];
            float a[8] = {a0.x, a0.y, a0.z, a0.w, a1.x, a1.y, a1.z, a1.w};
            float b[4] = {bv.x, bv.y, bv.z, bv.w};
            #pragma unroll
            for (int i = 0; i < 8; i++)
                #pragma unroll
                for (int j = 0; j < 4; j++)
                    acc[i][j] += a[i] * b[j];
        }
        if (has_next) {
            int nb = buf ^ 1;
            As[nb][akk + 0][amm] = na0.x; As[nb][akk + 1][amm] = na0.y;
            As[nb][akk + 2][amm] = na0.z; As[nb][akk + 3][amm] = na0.w;
            As[nb][akk + 4][amm] = na1.x; As[nb][akk + 5][amm] = na1.y;
            As[nb][akk + 6][amm] = na1.z; As[nb][akk + 7][amm] = na1.w;
            Bs[nb][bkk][bnn]     = nbv.x; Bs[nb][bkk][bnn + 1] = nbv.y;
            Bs[nb][bkk][bnn + 2] = nbv.z; Bs[nb][bkk][bnn + 3] = nbv.w;
            __syncthreads();
        }
    }

    #pragma unroll
    for (int i = 0; i < 8; i++) {
        int r = row0 + tm + i;
        if (r < M) {
            float4 v = make_float4(acc[i][0], acc[i][1], acc[i][2], acc[i][3]);
            *(float4*)(C + (size_t)r * Ncol + col0 + tn) = v;
        }
    }

    // ---- fused attention-coefficient epilogue ----
    if (mode == 1) {
        int gc = col0 + tn;
        int h  = gc >> 5;
        int cc = gc & 31;
        float4 asv = *(const float4*)(a_src + h * HID + cc);
        float4 adv = *(const float4*)(a_dst + h * HID + cc);
        #pragma unroll
        for (int i = 0; i < 8; i++) {
            float sv = acc[i][0] * asv.x + acc[i][1] * asv.y
                     + acc[i][2] * asv.z + acc[i][3] * asv.w;
            float dv = acc[i][0] * adv.x + acc[i][1] * adv.y
                     + acc[i][2] * adv.z + acc[i][3] * adv.w;
            #pragma unroll
            for (int off = 4; off > 0; off >>= 1) {
                sv += __shfl_down_sync(0xffffffffu, sv, off, 8);
                dv += __shfl_down_sync(0xffffffffu, dv, off, 8);
            }
            int r = row0 + tm + i;
            if ((tid & 7) == 0 && r < M) {
                g_as1[r * 8 + h] = sv;
                g_ad1[r * 8 + h] = dv;
            }
        }
    } else if (mode == 2) {
        int gc = col0 + tn;
        float4 asv = *(const float4*)(a_src + gc);
        float4 adv = *(const float4*)(a_dst + gc);
        #pragma unroll
        for (int i = 0; i < 8; i++) {
            float sv = acc[i][0] * asv.x + acc[i][1] * asv.y
                     + acc[i][2] * asv.z + acc[i][3] * asv.w;
            float dv = acc[i][0] * adv.x + acc[i][1] * adv.y
                     + acc[i][2] * adv.z + acc[i][3] * adv.w;
            #pragma unroll
            for (int off = 8; off > 0; off >>= 1) {
                sv += __shfl_down_sync(0xffffffffu, sv, off, 16);
                dv += __shfl_down_sync(0xffffffffu, dv, off, 16);
            }
            int r = row0 + tm + i;
            if ((tid & 15) == 0 && r < M) {
                g_as2[r] = sv;
                g_ad2[r] = dv;
            }
        }
    }
}

// ---------------- CSR aggregation layer 1: one warp per dst node ----------
// lane owns channels c = lane*8 + q; head of lane = lane>>2.
// softmax without max-shift: shift-invariant; logits are O(1) (no overflow)
__global__ void aggregate1(const float* __restrict__ b1) {
    __shared__ int   ss[8][32];
    __shared__ float ws[8][32][8];
    int w = (blockIdx.x * blockDim.x + threadIdx.x) >> 5;
    if (w >= N_) return;
    int lane = threadIdx.x & 31;
    int wb   = (threadIdx.x >> 5) & 7;
    int beg = g_roff[w], end = g_roff[w + 1];

    float ad[8];
    {
        float4 d0 = *(const float4*)(g_ad1 + w * 8);
        float4 d1 = *(const float4*)(g_ad1 + w * 8 + 4);
        ad[0] = d0.x; ad[1] = d0.y; ad[2] = d0.z; ad[3] = d0.w;
        ad[4] = d1.x; ad[5] = d1.y; ad[6] = d1.z; ad[7] = d1.w;
    }

    float acc[8] = {};
    float zp[8]  = {};
    int hsel = lane >> 2;

    for (int base = beg; base < end; base += 32) {
        int cnt = min(32, end - base);
        __syncwarp();   // WAR vs previous chunk's reads (uniform trip count per warp)
        if (base + lane < end) {
            int s = g_csr_src[base + lane];
            ss[wb][lane] = s;
            float4 s0 = *(const float4*)(g_as1 + s * 8);
            float4 s1 = *(const float4*)(g_as1 + s * 8 + 4);
            float ev[8] = {s0.x + ad[0], s0.y + ad[1], s0.z + ad[2], s0.w + ad[3],
                           s1.x + ad[4], s1.y + ad[5], s1.z + ad[6], s1.w + ad[7]};
            #pragma unroll
            for (int h = 0; h < 8; h++) {
                float e = ev[h];
                e = (e >= 0.f) ? e : NEG_SLOPE * e;
                float wv = __expf(e);
                ws[wb][lane][h] = wv;
                zp[h] += wv;
            }
        }
        __syncwarp();
        for (int j = 0; j < cnt; j++) {
            int s = ss[wb][j];
            float wj = ws[wb][j][hsel];
            const float* hs = g_h1 + (size_t)s * F1 + lane * 8;
            float4 p0 = *(const float4*)hs;
            float4 p1 = *(const float4*)(hs + 4);
            acc[0] += wj * p0.x; acc[1] += wj * p0.y;
            acc[2] += wj * p0.z; acc[3] += wj * p0.w;
            acc[4] += wj * p1.x; acc[5] += wj * p1.y;
            acc[6] += wj * p1.z; acc[7] += wj * p1.w;
        }
    }

    #pragma unroll
    for (int h = 0; h < 8; h++)
        #pragma unroll
        for (int off = 16; off > 0; off >>= 1)
            zp[h] += __shfl_xor_sync(0xffffffffu, zp[h], off);
    float zu = zp[0];
    #pragma unroll
    for (int h = 1; h < 8; h++)
        if (hsel == h) zu = zp[h];

    float inv = (zu > 0.f) ? (1.f / zu) : 0.f;
    const float* bp = b1 + lane * 8;
    float4 b0 = *(const float4*)bp;
    float4 b1v = *(const float4*)(bp + 4);
    float bb[8] = {b0.x, b0.y, b0.z, b0.w, b1v.x, b1v.y, b1v.z, b1v.w};
    float o[8];
    #pragma unroll
    for (int q = 0; q < 8; q++) {
        float v = acc[q] * inv + bb[q];
        o[q] = (v > 0.f) ? v : (__expf(v) - 1.f);   // ELU
    }
    float* op = g_hact + (size_t)w * F1 + lane * 8;
    *(float4*)op       = make_float4(o[0], o[1], o[2], o[3]);
    *(float4*)(op + 4) = make_float4(o[4], o[5], o[6], o[7]);
}

// ---------------- CSR aggregation layer 2: HALF-warp per dst node ---------
// 2 nodes per warp; 16 lanes per node, each lane owns 4 channels (float4).
// All intra-loop syncs use the half-specific 16-lane mask: the two halves
// have different trip counts, so full-warp syncs inside the loop are UB.
__global__ void aggregate2(const float* __restrict__ b2, float* __restrict__ out) {
    __shared__ int   ss[8][2][16];
    __shared__ float ws[8][2][16];
    int warp = (blockIdx.x * blockDim.x + threadIdx.x) >> 5;
    int lane = threadIdx.x & 31;
    int wb   = (threadIdx.x >> 5) & 7;
    int half = lane >> 4;          // which node within the warp
    int l16  = lane & 15;          // lane within the half-warp
    unsigned hmask = 0xFFFFu << (half * 16);
    int w = warp * 2 + half;
    if (w >= N_) return;

    int beg = g_roff[w], end = g_roff[w + 1];
    float adn = g_ad2[w];

    float4 acc = make_float4(0.f, 0.f, 0.f, 0.f);
    float zp = 0.f;

    for (int base = beg; base < end; base += 16) {
        int cnt = min(16, end - base);
        __syncwarp(hmask);         // WAR vs previous chunk (this half only)
        if (base + l16 < end) {
            int s = g_csr_src[base + l16];
            ss[wb][half][l16] = s;
            float e = g_as2[s] + adn;
            e = (e >= 0.f) ? e : NEG_SLOPE * e;
            float wv = __expf(e);
            ws[wb][half][l16] = wv;
            zp += wv;
        }
        __syncwarp(hmask);
        for (int j = 0; j < cnt; j++) {
            int s = ss[wb][half][j];
            float wj = ws[wb][half][j];
            float4 hv = *(const float4*)(g_h2 + (size_t)s * OUTC + l16 * 4);
            acc.x += wj * hv.x; acc.y += wj * hv.y;
            acc.z += wj * hv.z; acc.w += wj * hv.w;
        }
    }
    // reduce z across the 16 lanes of this half-warp (half-specific mask)
    #pragma unroll
    for (int off = 8; off > 0; off >>= 1)
        zp += __shfl_xor_sync(hmask, zp, off, 16);
    float inv = (zp > 0.f) ? (1.f / zp) : 0.f;
    float4 bv = *(const float4*)(b2 + l16 * 4);
    float4 ov = make_float4(acc.x * inv + bv.x, acc.y * inv + bv.y,
                            acc.z * inv + bv.z, acc.w * inv + bv.w);
    *(float4*)(out + (size_t)w * OUTC + l16 * 4) = ov;
}

// ---------------- launch ----------------
extern "C" void kernel_launch(void* const* d_in, const int* in_sizes, int n_in,
                              void* d_out, int out_size) {
    const float* x    = (const float*)d_in[0];
    const int*   ei32 = (const int*)d_in[1];
    const float* W1   = (const float*)d_in[2];
    const float* a1s  = (const float*)d_in[3];
    const float* a1d  = (const float*)d_in[4];
    const float* b1   = (const float*)d_in[5];
    const float* W2   = (const float*)d_in[6];
    const float* a2s  = (const float*)d_in[7];
    const float* a2d  = (const float*)d_in[8];
    const float* b2   = (const float*)d_in[9];
    float* out = (float*)d_out;

    void* p;
    cudaGetSymbolAddress(&p, g_h1);   float* h1   = (float*)p;
    cudaGetSymbolAddress(&p, g_hact); float* hact = (float*)p;
    cudaGetSymbolAddress(&p, g_h2);   float* h2   = (float*)p;

    cudaStream_t s2 = g_ss.s2 ? g_ss.s2 : (cudaStream_t)0;
    bool forked = (g_ss.s2 != nullptr) && g_ss.fork && g_ss.join;

    // fork: graph build (CSR) on side stream, concurrent with GEMM1
    if (forked) {
        cudaEventRecord(g_ss.fork, 0);
        cudaStreamWaitEvent(s2, g_ss.fork, 0);
    }
    zero_deg_probe<<<(N_ + 255) / 256, 256, 0, s2>>>(ei32);
    count_deg<<<(E_ + 255) / 256, 256, 0, s2>>>(ei32);
    scan_p1<<<NB_SCAN, 256, 0, s2>>>();
    scan_p2<<<1, 256, 0, s2>>>();
    scan_p3<<<NB_SCAN, 256, 0, s2>>>();
    build_csr<<<(E_ + 255) / 256, 256, 0, s2>>>(ei32);
    if (forked) cudaEventRecord(g_ss.join, s2);

    // layer 1 GEMM (alpha fused, mode 1) on main stream, overlaps build
    {
        dim3 grid(F1 / 64, (N_ + 127) / 128);
        sgemm128x64<<<grid, 256>>>(x, W1, h1, N_, INC, F1, 1, a1s, a1d);
    }
    if (forked) cudaStreamWaitEvent((cudaStream_t)0, g_ss.join, 0);

    aggregate1<<<(N_ * 32 + 255) / 256, 256>>>(b1);

    // layer 2 (alpha fused, mode 2)
    {
        dim3 grid(OUTC / 64, (N_ + 127) / 128);
        sgemm128x64<<<grid, 256>>>(hact, W2, h2, N_, F1, OUTC, 2, a2s, a2d);
    }
    aggregate2<<<((N_ + 1) / 2 * 32 + 255) / 256, 256>>>(b2, out);
}